// round 11
// baseline (speedup 1.0000x reference)
#include <cuda_runtime.h>
#include <cuda_fp16.h>
#include <cstdint>

#define H_HEADS 16
#define DHEAD 128
#define SEQ 2048
#define BATCH 2
#define CDIM 2048
#define WIN 256

#define GK 2048
#define GN 2048
#define GM 4096

#define QKV_ELEMS ((size_t)BATCH * H_HEADS * SEQ * DHEAD)   // 8388608
#define WMAT_ELEMS ((size_t)GK * GN)                        // 4194304 = 2^22
#define XEL (GM * GK)                                       // 8388608 = 2^23

// fp16 scratch
__device__ __half g_qkvh[3 * QKV_ELEMS];     // Q,K,V in (B,H,L,D)
__device__ __half g_xh[(size_t)XEL];
__device__ __half g_wh[4 * WMAT_ELEMS];      // Wq,Wk,Wv,Wo
__device__ __half g_aoh[(size_t)GM * CDIM];

// ---------------------------------------------------------------------------
__device__ __forceinline__ void mma16(float* c, const uint32_t* a, uint32_t b0, uint32_t b1) {
    asm volatile(
        "mma.sync.aligned.m16n8k16.row.col.f32.f16.f16.f32 "
        "{%0,%1,%2,%3},{%4,%5,%6,%7},{%8,%9},{%0,%1,%2,%3};\n"
        : "+f"(c[0]), "+f"(c[1]), "+f"(c[2]), "+f"(c[3])
        : "r"(a[0]), "r"(a[1]), "r"(a[2]), "r"(a[3]), "r"(b0), "r"(b1));
}

__device__ __forceinline__ void ldsm4(uint32_t* r, uint32_t addr) {
    asm volatile("ldmatrix.sync.aligned.m8n8.x4.shared.b16 {%0,%1,%2,%3}, [%4];"
                 : "=r"(r[0]), "=r"(r[1]), "=r"(r[2]), "=r"(r[3]) : "r"(addr));
}
__device__ __forceinline__ void ldsm4t(uint32_t* r, uint32_t addr) {
    asm volatile("ldmatrix.sync.aligned.m8n8.x4.trans.shared.b16 {%0,%1,%2,%3}, [%4];"
                 : "=r"(r[0]), "=r"(r[1]), "=r"(r[2]), "=r"(r[3]) : "r"(addr));
}

__device__ __forceinline__ uint32_t smem_u32(const void* p) {
    uint32_t a;
    asm("{ .reg .u64 t; cvta.to.shared.u64 t, %1; cvt.u32.u64 %0, t; }" : "=r"(a) : "l"(p));
    return a;
}

__device__ __forceinline__ void cp16(uint32_t dst, const void* src) {
    asm volatile("cp.async.cg.shared.global [%0], [%1], 16;\n" :: "r"(dst), "l"(src));
}
__device__ __forceinline__ void cp_commit() { asm volatile("cp.async.commit_group;\n"); }
template<int N> __device__ __forceinline__ void cp_wait() {
    asm volatile("cp.async.wait_group %0;\n" :: "n"(N));
}

// ---------------------------------------------------------------------------
// fused fp32 -> fp16 conversion: x (XEL elems) then 4 weight matrices
// ---------------------------------------------------------------------------
__global__ void cvt_all(const float* __restrict__ x,
                        const float* __restrict__ w0, const float* __restrict__ w1,
                        const float* __restrict__ w2, const float* __restrict__ w3,
                        __half* __restrict__ xh, __half* __restrict__ wh)
{
    int t = blockIdx.x * blockDim.x + threadIdx.x;
    size_t i = (size_t)t * 8;
    const float* in;
    __half* out;
    if (i < (size_t)XEL) {
        in = x + i;
        out = xh + i;
    } else {
        size_t j = i - XEL;
        int m = (int)(j >> 22);
        size_t r = j & (WMAT_ELEMS - 1);
        in = ((m == 0) ? w0 : (m == 1) ? w1 : (m == 2) ? w2 : w3) + r;
        out = wh + (size_t)m * WMAT_ELEMS + r;
    }
    float4 a = *(const float4*)in;
    float4 b = *(const float4*)(in + 4);
    __half2 h0 = __floats2half2_rn(a.x, a.y);
    __half2 h1 = __floats2half2_rn(a.z, a.w);
    __half2 h2 = __floats2half2_rn(b.x, b.y);
    __half2 h3 = __floats2half2_rn(b.z, b.w);
    *(uint4*)out = make_uint4(*(uint32_t*)&h0, *(uint32_t*)&h1,
                              *(uint32_t*)&h2, *(uint32_t*)&h3);
}

// ---------------------------------------------------------------------------
// FP16 GEMM, cp.async 4-stage pipeline + ldmatrix (proven round-9 config).
// Tile 128x128x32, 8 warps (4x2). Smem tile: 64 rows x 128B; row s holds
// m-rows {2s,2s+1}; chunk = ((m&1)*4 + k8) ^ (s&7).
// fused=1: grid.y in [0,48): matrix mi=y/16 -> fp16 scatter (B,H,L,D).
// fused=0: fp32 row-major out.
// ---------------------------------------------------------------------------
#define TBM 128
#define TBN 128
#define BK 32
#define KT (GK / BK)      // 64
#define TILE_BYTES 8192
#define NST 4
#define GEMM_SMEM (NST * 2 * TILE_BYTES)   // 64 KB

__global__ __launch_bounds__(256, 2)
void gemm_ca(const __half* __restrict__ A, const __half* __restrict__ Wh,
             const float* __restrict__ bias0, const float* __restrict__ bias1,
             const float* __restrict__ bias2,
             float* __restrict__ outf, __half* __restrict__ outh, int fused)
{
    extern __shared__ __align__(16) char smem[];
    uint32_t sbase = smem_u32(smem);

    int tid = threadIdx.x;
    int wid = tid >> 5, lane = tid & 31;
    int g = lane >> 2, tg = lane & 3;
    int wm = wid >> 1, wn = wid & 1;
    int m0 = blockIdx.x * TBM;

    int n0;
    const float* bias = bias0;
    const __half* W = Wh;
    __half* outp = outh;
    if (fused) {
        int mi = blockIdx.y >> 4;
        n0 = (blockIdx.y & 15) * TBN;
        W = Wh + (size_t)mi * WMAT_ELEMS;
        bias = (mi == 0) ? bias0 : (mi == 1) ? bias1 : bias2;
        outp = outh + (size_t)mi * QKV_ELEMS;
    } else {
        n0 = blockIdx.y * TBN;
    }

    int pm = tid >> 1;
    int ps = pm >> 1;
    int pre0 = (pm & 1) * 4 + (tid & 1) * 2;
    uint32_t pOff0 = (uint32_t)(ps * 128 + ((pre0 ^ (ps & 7)) * 16));
    uint32_t pOff1 = (uint32_t)(ps * 128 + (((pre0 + 1) ^ (ps & 7)) * 16));
    const __half* gA = A + (size_t)(m0 + pm) * GK + (tid & 1) * 16;
    const __half* gW = W + (size_t)(n0 + pm) * GK + (tid & 1) * 16;

    uint32_t aAdr[2], bAdr[4];
    #pragma unroll
    for (int mt = 0; mt < 2; mt++) {
        int m = wm * 32 + mt * 16 + (lane & 7) + 8 * ((lane >> 3) & 1);
        int k8 = lane >> 4;
        int s = m >> 1;
        int chunk = (((m & 1) * 4 + k8) ^ (s & 7));
        aAdr[mt] = (uint32_t)(s * 128 + chunk * 16);
    }
    #pragma unroll
    for (int nq = 0; nq < 4; nq++) {
        int n = wn * 64 + nq * 16 + (lane & 7) + 8 * (lane >> 4);
        int k8 = (lane >> 3) & 1;
        int s = n >> 1;
        int chunk = (((n & 1) * 4 + k8) ^ (s & 7));
        bAdr[nq] = (uint32_t)(s * 128 + chunk * 16);
    }

    float acc[2][8][4];
    #pragma unroll
    for (int mt = 0; mt < 2; mt++)
        #pragma unroll
        for (int nt = 0; nt < 8; nt++)
            #pragma unroll
            for (int i = 0; i < 4; i++) acc[mt][nt][i] = 0.f;

    #pragma unroll
    for (int s = 0; s < NST - 1; s++) {
        uint32_t aT = sbase + s * (2 * TILE_BYTES);
        uint32_t bT = aT + TILE_BYTES;
        const __half* sa = gA + s * BK;
        const __half* sb = gW + s * BK;
        cp16(aT + pOff0, sa);
        cp16(aT + pOff1, sa + 8);
        cp16(bT + pOff0, sb);
        cp16(bT + pOff1, sb + 8);
        cp_commit();
    }

    for (int kt = 0; kt < KT; kt++) {
        cp_wait<NST - 2>();
        __syncthreads();

        if (kt + NST - 1 < KT) {
            int st = (kt + NST - 1) & (NST - 1);
            uint32_t aT = sbase + st * (2 * TILE_BYTES);
            uint32_t bT = aT + TILE_BYTES;
            const __half* sa = gA + (kt + NST - 1) * BK;
            const __half* sb = gW + (kt + NST - 1) * BK;
            cp16(aT + pOff0, sa);
            cp16(aT + pOff1, sa + 8);
            cp16(bT + pOff0, sb);
            cp16(bT + pOff1, sb + 8);
        }
        cp_commit();

        int buf = kt & (NST - 1);
        uint32_t ab = sbase + buf * (2 * TILE_BYTES);
        uint32_t bb = ab + TILE_BYTES;
        #pragma unroll
        for (int ks = 0; ks < 2; ks++) {
            uint32_t kx = ks ? 32u : 0u;
            uint32_t af0[4], af1[4];
            ldsm4(af0, ab + (aAdr[0] ^ kx));
            ldsm4(af1, ab + (aAdr[1] ^ kx));
            #pragma unroll
            for (int nq = 0; nq < 4; nq++) {
                uint32_t bf[4];
                ldsm4(bf, bb + (bAdr[nq] ^ kx));
                mma16(acc[0][2 * nq],     af0, bf[0], bf[1]);
                mma16(acc[0][2 * nq + 1], af0, bf[2], bf[3]);
                mma16(acc[1][2 * nq],     af1, bf[0], bf[1]);
                mma16(acc[1][2 * nq + 1], af1, bf[2], bf[3]);
            }
        }
    }

    #pragma unroll
    for (int mt = 0; mt < 2; mt++) {
        #pragma unroll
        for (int nt = 0; nt < 8; nt++) {
            int r = m0 + wm * 32 + mt * 16 + g;
            int c = n0 + wn * 64 + nt * 8 + 2 * tg;
            float bv0 = __ldg(&bias[c]), bv1 = __ldg(&bias[c + 1]);
            float v00 = acc[mt][nt][0] + bv0, v01 = acc[mt][nt][1] + bv1;
            float v10 = acc[mt][nt][2] + bv0, v11 = acc[mt][nt][3] + bv1;
            if (!fused) {
                *(float2*)&outf[(size_t)r * GN + c]       = make_float2(v00, v01);
                *(float2*)&outf[(size_t)(r + 8) * GN + c] = make_float2(v10, v11);
            } else {
                int b = r >> 11, l = r & 2047;
                int h = c >> 7, d = c & 127;
                size_t base2 = ((size_t)(b * H_HEADS + h) * SEQ + l) * DHEAD + d;
                __half2 h0 = __floats2half2_rn(v00, v01);
                __half2 h1 = __floats2half2_rn(v10, v11);
                *(__half2*)&outp[base2]                     = h0;
                *(__half2*)&outp[base2 + (size_t)8 * DHEAD] = h1;
            }
        }
    }
}

// ---------------------------------------------------------------------------
// Sliding-window flash attention, fp16 mma + ldmatrix, double-buffered
// cp.async K/V pipeline. Smem: 2 x (K 16KB + V 16KB) + P 16KB = 80KB.
// ---------------------------------------------------------------------------
#define ATT_SMEM 81920

__global__ __launch_bounds__(256, 1)
void attn_h16(const __half* __restrict__ qg, const __half* __restrict__ kg,
              const __half* __restrict__ vg, __half* __restrict__ aout)
{
    extern __shared__ __align__(16) char sm[];
    uint32_t sb = smem_u32(sm);
    uint32_t Ps = sb + 65536;

    int tid = threadIdx.x;
    int wid = tid >> 5, lane = tid & 31, g = lane >> 2, tg = lane & 3;
    int q0 = blockIdx.x * 128;
    int bh = blockIdx.y;
    const __half* qb = qg + (size_t)bh * SEQ * DHEAD;
    const __half* kb = kg + (size_t)bh * SEQ * DHEAD;
    const __half* vb = vg + (size_t)bh * SEQ * DHEAD;
    int b = bh >> 4, h = bh & 15;

    // ---- stage Q (128 x 256B) in buffer0 area, load fragments ----
    #pragma unroll
    for (int e = tid; e < 2048; e += 256) {
        int r = e >> 4, c = e & 15;
        uint4 v = *(const uint4*)&qb[(size_t)(q0 + r) * DHEAD + c * 8];
        *(uint4*)(sm + r * 256 + ((c ^ (r & 7)) * 16)) = v;
    }
    __syncthreads();

    uint32_t qa[8][4];
    {
        int qrow = wid * 16 + (lane & 7) + 8 * ((lane >> 3) & 1);
        #pragma unroll
        for (int ks = 0; ks < 8; ks++) {
            int c = ks * 2 + (lane >> 4);
            ldsm4(qa[ks], sb + qrow * 256 + ((c ^ (qrow & 7)) * 16));
        }
    }
    __syncthreads();

    // chunk list (diagonal first)
    const int offs[6] = {0, 1, -1, -2, -3, -4};
    int k0s[6], nch = 0;
    #pragma unroll
    for (int ci = 0; ci < 6; ci++) {
        int k0 = q0 + offs[ci] * 64;
        if (k0 >= 0) k0s[nch++] = k0;
    }

    auto issue_kv = [&](int k0, int bf) {
        uint32_t dbase = sb + (uint32_t)bf * 32768u;
        #pragma unroll
        for (int j = 0; j < 8; j++) {
            int e = tid + j * 256;
            int which = e >> 10, i = e & 1023;
            int r = i >> 4, c = i & 15;
            const __half* src = which ? vb : kb;
            cp16(dbase + which * 16384 + (uint32_t)(r * 256 + ((c ^ (r & 7)) * 16)),
                 &src[(size_t)(k0 + r) * DHEAD + c * 8]);
        }
    };

    issue_kv(k0s[0], 0);
    cp_commit();

    float o[16][4];
    #pragma unroll
    for (int nt = 0; nt < 16; nt++)
        #pragma unroll
        for (int i = 0; i < 4; i++) o[nt][i] = 0.f;
    float mrow0 = -1e30f, mrow1 = -1e30f, lsum0 = 0.f, lsum1 = 0.f;

    const float scale = 0.088388347648318447f;

    int kRow = (lane & 7) + 8 * (lane >> 4);
    int kK8  = (lane >> 3) & 1;
    int pRow = wid * 16 + (lane & 7) + 8 * ((lane >> 3) & 1);
    int pK8  = lane >> 4;
    int vRow = (lane & 7) + 8 * ((lane >> 3) & 1);
    int vK8  = lane >> 4;
    int pr0 = wid * 16 + g, pr1 = pr0 + 8;

    for (int ci = 0; ci < nch; ci++) {
        int k0 = k0s[ci];
        __syncthreads();
        if (ci + 1 < nch) issue_kv(k0s[ci + 1], (ci + 1) & 1);
        cp_commit();
        cp_wait<1>();
        __syncthreads();

        uint32_t Ks = sb + (uint32_t)(ci & 1) * 32768u;
        uint32_t Vs = Ks + 16384u;

        // ---- S = Q K^T ----
        float s[8][4];
        #pragma unroll
        for (int nt = 0; nt < 8; nt++)
            #pragma unroll
            for (int i = 0; i < 4; i++) s[nt][i] = 0.f;
        #pragma unroll
        for (int ks = 0; ks < 8; ks++) {
            int c = ks * 2 + kK8;
            #pragma unroll
            for (int nq = 0; nq < 4; nq++) {
                int row = nq * 16 + kRow;
                uint32_t bf[4];
                ldsm4(bf, Ks + row * 256 + ((c ^ (row & 7)) * 16));
                mma16(s[2 * nq],     qa[ks], bf[0], bf[1]);
                mma16(s[2 * nq + 1], qa[ks], bf[2], bf[3]);
            }
        }

        // ---- mask + online softmax ----
        int i0 = q0 + pr0, i1 = i0 + 8;
        float mx0 = -1e30f, mx1 = -1e30f;
        #pragma unroll
        for (int nt = 0; nt < 8; nt++) {
            int j0 = k0 + nt * 8 + 2 * tg, j1 = j0 + 1;
            s[nt][0] = ((j0 <= i0) && (j0 > i0 - WIN)) ? s[nt][0] * scale : -1e30f;
            s[nt][1] = ((j1 <= i0) && (j1 > i0 - WIN)) ? s[nt][1] * scale : -1e30f;
            s[nt][2] = ((j0 <= i1) && (j0 > i1 - WIN)) ? s[nt][2] * scale : -1e30f;
            s[nt][3] = ((j1 <= i1) && (j1 > i1 - WIN)) ? s[nt][3] * scale : -1e30f;
            mx0 = fmaxf(mx0, fmaxf(s[nt][0], s[nt][1]));
            mx1 = fmaxf(mx1, fmaxf(s[nt][2], s[nt][3]));
        }
        mx0 = fmaxf(mx0, __shfl_xor_sync(0xffffffffu, mx0, 1));
        mx0 = fmaxf(mx0, __shfl_xor_sync(0xffffffffu, mx0, 2));
        mx1 = fmaxf(mx1, __shfl_xor_sync(0xffffffffu, mx1, 1));
        mx1 = fmaxf(mx1, __shfl_xor_sync(0xffffffffu, mx1, 2));
        float mn0 = fmaxf(mrow0, mx0), mn1 = fmaxf(mrow1, mx1);
        float al0 = __expf(mrow0 - mn0), al1 = __expf(mrow1 - mn1);
        mrow0 = mn0; mrow1 = mn1;

        float rs0 = 0.f, rs1 = 0.f;
        #pragma unroll
        for (int nt = 0; nt < 8; nt++) {
            s[nt][0] = __expf(s[nt][0] - mn0);
            s[nt][1] = __expf(s[nt][1] - mn0);
            s[nt][2] = __expf(s[nt][2] - mn1);
            s[nt][3] = __expf(s[nt][3] - mn1);
            rs0 += s[nt][0] + s[nt][1];
            rs1 += s[nt][2] + s[nt][3];
        }
        rs0 += __shfl_xor_sync(0xffffffffu, rs0, 1);
        rs0 += __shfl_xor_sync(0xffffffffu, rs0, 2);
        rs1 += __shfl_xor_sync(0xffffffffu, rs1, 1);
        rs1 += __shfl_xor_sync(0xffffffffu, rs1, 2);
        lsum0 = lsum0 * al0 + rs0;
        lsum1 = lsum1 * al1 + rs1;

        // ---- P -> fp16 smem (warp-private rows) ----
        #pragma unroll
        for (int nt = 0; nt < 8; nt++) {
            __half2 p0 = __floats2half2_rn(s[nt][0], s[nt][1]);
            __half2 p1 = __floats2half2_rn(s[nt][2], s[nt][3]);
            *(__half2*)(sm + 65536 + pr0 * 128 + ((nt ^ (pr0 & 7)) * 16) + 4 * tg) = p0;
            *(__half2*)(sm + 65536 + pr1 * 128 + ((nt ^ (pr1 & 7)) * 16) + 4 * tg) = p1;
        }
        __syncwarp();

        #pragma unroll
        for (int nt = 0; nt < 16; nt++) {
            o[nt][0] *= al0; o[nt][1] *= al0;
            o[nt][2] *= al1; o[nt][3] *= al1;
        }

        // ---- O += P V ----
        #pragma unroll
        for (int ks = 0; ks < 4; ks++) {
            uint32_t pa[4];
            {
                int c = ks * 2 + pK8;
                ldsm4(pa, Ps + pRow * 128 + ((c ^ (pRow & 7)) * 16));
            }
            int row = ks * 16 + vRow;
            uint32_t vbase = Vs + row * 256;
            int rx = row & 7;
            #pragma unroll
            for (int dt = 0; dt < 8; dt++) {
                int c = dt * 2 + vK8;
                uint32_t bf[4];
                ldsm4t(bf, vbase + ((c ^ rx) * 16));
                mma16(o[2 * dt],     pa, bf[0], bf[1]);
                mma16(o[2 * dt + 1], pa, bf[2], bf[3]);
            }
        }
    }

    float inv0 = 1.f / lsum0, inv1 = 1.f / lsum1;
    int t0 = q0 + pr0;
    #pragma unroll
    for (int nt = 0; nt < 16; nt++) {
        int col = h * DHEAD + nt * 8 + 2 * tg;
        __half2 h0 = __floats2half2_rn(o[nt][0] * inv0, o[nt][1] * inv0);
        __half2 h1 = __floats2half2_rn(o[nt][2] * inv1, o[nt][3] * inv1);
        *(__half2*)&aout[((size_t)b * SEQ + t0) * CDIM + col]     = h0;
        *(__half2*)&aout[((size_t)b * SEQ + t0 + 8) * CDIM + col] = h1;
    }
}

// ---------------------------------------------------------------------------
extern "C" void kernel_launch(void* const* d_in, const int* in_sizes, int n_in,
                              void* d_out, int out_size)
{
    const float* x  = (const float*)d_in[0];
    const float* Wq = (const float*)d_in[1];
    const float* bq = (const float*)d_in[2];
    const float* Wk = (const float*)d_in[3];
    const float* bk = (const float*)d_in[4];
    const float* Wv = (const float*)d_in[5];
    const float* bv = (const float*)d_in[6];
    const float* Wo = (const float*)d_in[7];
    const float* bo = (const float*)d_in[8];
    float* out = (float*)d_out;

    __half *qkvh, *xh, *wh, *aoh;
    cudaGetSymbolAddress((void**)&qkvh, g_qkvh);
    cudaGetSymbolAddress((void**)&xh, g_xh);
    cudaGetSymbolAddress((void**)&wh, g_wh);
    cudaGetSymbolAddress((void**)&aoh, g_aoh);

    cudaFuncSetAttribute(gemm_ca, cudaFuncAttributeMaxDynamicSharedMemorySize, GEMM_SMEM);
    cudaFuncSetAttribute(attn_h16, cudaFuncAttributeMaxDynamicSharedMemorySize, ATT_SMEM);

    // fused conversions: x (2^23) + 4 weights (4 * 2^22) = 25165824 elems
    cvt_all<<<(25165824 / 8) / 256, 256>>>(x, Wq, Wk, Wv, Wo, xh, wh);

    // fused QKV GEMM -> fp16 (B,H,L,D)
    gemm_ca<<<dim3(GM / TBM, 48), 256, GEMM_SMEM>>>(xh, wh, bq, bk, bv, nullptr, qkvh, 1);

    // attention (fp16 in, fp16 out)
    attn_h16<<<dim3(SEQ / 128, BATCH * H_HEADS), 256, ATT_SMEM>>>(
        qkvh, qkvh + QKV_ELEMS, qkvh + 2 * QKV_ELEMS, aoh);

    // output projection -> fp32
    gemm_ca<<<dim3(GM / TBM, GN / TBN), 256, GEMM_SMEM>>>(
        aoh, wh + 3 * WMAT_ELEMS, bo, nullptr, nullptr, out, nullptr, 0);
}

// round 12
// speedup vs baseline: 1.4362x; 1.4362x over previous
#include <cuda_runtime.h>
#include <cuda_fp16.h>
#include <cstdint>

#define H_HEADS 16
#define DHEAD 128
#define SEQ 2048
#define BATCH 2
#define CDIM 2048
#define WIN 256

#define GK 2048
#define GN 2048
#define GM 4096

#define QKV_ELEMS ((size_t)BATCH * H_HEADS * SEQ * DHEAD)   // 8388608
#define WMAT_ELEMS ((size_t)GK * GN)                        // 4194304 = 2^22
#define XEL (GM * GK)                                       // 8388608 = 2^23

// fp16 scratch
__device__ __half g_qkvh[3 * QKV_ELEMS];     // Q,K,V in (B,H,L,D)
__device__ __half g_xh[(size_t)XEL];
__device__ __half g_wh[4 * WMAT_ELEMS];      // Wq,Wk,Wv,Wo
__device__ __half g_aoh[(size_t)GM * CDIM];

// ---------------------------------------------------------------------------
__device__ __forceinline__ void mma16(float* c, const uint32_t* a, uint32_t b0, uint32_t b1) {
    asm volatile(
        "mma.sync.aligned.m16n8k16.row.col.f32.f16.f16.f32 "
        "{%0,%1,%2,%3},{%4,%5,%6,%7},{%8,%9},{%0,%1,%2,%3};\n"
        : "+f"(c[0]), "+f"(c[1]), "+f"(c[2]), "+f"(c[3])
        : "r"(a[0]), "r"(a[1]), "r"(a[2]), "r"(a[3]), "r"(b0), "r"(b1));
}

__device__ __forceinline__ void ldsm4(uint32_t* r, uint32_t addr) {
    asm volatile("ldmatrix.sync.aligned.m8n8.x4.shared.b16 {%0,%1,%2,%3}, [%4];"
                 : "=r"(r[0]), "=r"(r[1]), "=r"(r[2]), "=r"(r[3]) : "r"(addr));
}
__device__ __forceinline__ void ldsm4t(uint32_t* r, uint32_t addr) {
    asm volatile("ldmatrix.sync.aligned.m8n8.x4.trans.shared.b16 {%0,%1,%2,%3}, [%4];"
                 : "=r"(r[0]), "=r"(r[1]), "=r"(r[2]), "=r"(r[3]) : "r"(addr));
}

__device__ __forceinline__ uint32_t smem_u32(const void* p) {
    uint32_t a;
    asm("{ .reg .u64 t; cvta.to.shared.u64 t, %1; cvt.u32.u64 %0, t; }" : "=r"(a) : "l"(p));
    return a;
}

__device__ __forceinline__ void cp16(uint32_t dst, const void* src) {
    asm volatile("cp.async.cg.shared.global [%0], [%1], 16;\n" :: "r"(dst), "l"(src));
}
__device__ __forceinline__ void cp_commit() { asm volatile("cp.async.commit_group;\n"); }
template<int N> __device__ __forceinline__ void cp_wait() {
    asm volatile("cp.async.wait_group %0;\n" :: "n"(N));
}

// ---------------------------------------------------------------------------
// fused fp32 -> fp16 conversion: x (XEL elems) then 4 weight matrices
// ---------------------------------------------------------------------------
__global__ void cvt_all(const float* __restrict__ x,
                        const float* __restrict__ w0, const float* __restrict__ w1,
                        const float* __restrict__ w2, const float* __restrict__ w3,
                        __half* __restrict__ xh, __half* __restrict__ wh)
{
    int t = blockIdx.x * blockDim.x + threadIdx.x;
    size_t i = (size_t)t * 8;
    const float* in;
    __half* out;
    if (i < (size_t)XEL) {
        in = x + i;
        out = xh + i;
    } else {
        size_t j = i - XEL;
        int m = (int)(j >> 22);
        size_t r = j & (WMAT_ELEMS - 1);
        in = ((m == 0) ? w0 : (m == 1) ? w1 : (m == 2) ? w2 : w3) + r;
        out = wh + (size_t)m * WMAT_ELEMS + r;
    }
    float4 a = *(const float4*)in;
    float4 b = *(const float4*)(in + 4);
    __half2 h0 = __floats2half2_rn(a.x, a.y);
    __half2 h1 = __floats2half2_rn(a.z, a.w);
    __half2 h2 = __floats2half2_rn(b.x, b.y);
    __half2 h3 = __floats2half2_rn(b.z, b.w);
    *(uint4*)out = make_uint4(*(uint32_t*)&h0, *(uint32_t*)&h1,
                              *(uint32_t*)&h2, *(uint32_t*)&h3);
}

// ---------------------------------------------------------------------------
// FP16 GEMM, cp.async 6-stage pipeline + ldmatrix.
// Tile 128x128x32, 8 warps (4x2). Smem tile: 64 rows x 128B; row s holds
// m-rows {2s,2s+1}; chunk = ((m&1)*4 + k8) ^ (s&7).
// fused=1: grid.y in [0,48): matrix mi=y/16 -> fp16 scatter (B,H,L,D).
// fused=0: fp32 row-major out.
// ---------------------------------------------------------------------------
#define TBM 128
#define TBN 128
#define BK 32
#define KT (GK / BK)      // 64
#define TILE_BYTES 8192
#define NST 6
#define GEMM_SMEM (NST * 2 * TILE_BYTES)   // 96 KB

__global__ __launch_bounds__(256, 2)
void gemm_ca(const __half* __restrict__ A, const __half* __restrict__ Wh,
             const float* __restrict__ bias0, const float* __restrict__ bias1,
             const float* __restrict__ bias2,
             float* __restrict__ outf, __half* __restrict__ outh, int fused)
{
    extern __shared__ __align__(16) char smem[];
    uint32_t sbase = smem_u32(smem);

    int tid = threadIdx.x;
    int wid = tid >> 5, lane = tid & 31;
    int g = lane >> 2, tg = lane & 3;
    int wm = wid >> 1, wn = wid & 1;
    int m0 = blockIdx.x * TBM;

    int n0;
    const float* bias = bias0;
    const __half* W = Wh;
    __half* outp = outh;
    if (fused) {
        int mi = blockIdx.y >> 4;
        n0 = (blockIdx.y & 15) * TBN;
        W = Wh + (size_t)mi * WMAT_ELEMS;
        bias = (mi == 0) ? bias0 : (mi == 1) ? bias1 : bias2;
        outp = outh + (size_t)mi * QKV_ELEMS;
    } else {
        n0 = blockIdx.y * TBN;
    }

    int pm = tid >> 1;
    int ps = pm >> 1;
    int pre0 = (pm & 1) * 4 + (tid & 1) * 2;
    uint32_t pOff0 = (uint32_t)(ps * 128 + ((pre0 ^ (ps & 7)) * 16));
    uint32_t pOff1 = (uint32_t)(ps * 128 + (((pre0 + 1) ^ (ps & 7)) * 16));
    const __half* gA = A + (size_t)(m0 + pm) * GK + (tid & 1) * 16;
    const __half* gW = W + (size_t)(n0 + pm) * GK + (tid & 1) * 16;

    uint32_t aAdr[2], bAdr[4];
    #pragma unroll
    for (int mt = 0; mt < 2; mt++) {
        int m = wm * 32 + mt * 16 + (lane & 7) + 8 * ((lane >> 3) & 1);
        int k8 = lane >> 4;
        int s = m >> 1;
        int chunk = (((m & 1) * 4 + k8) ^ (s & 7));
        aAdr[mt] = (uint32_t)(s * 128 + chunk * 16);
    }
    #pragma unroll
    for (int nq = 0; nq < 4; nq++) {
        int n = wn * 64 + nq * 16 + (lane & 7) + 8 * (lane >> 4);
        int k8 = (lane >> 3) & 1;
        int s = n >> 1;
        int chunk = (((n & 1) * 4 + k8) ^ (s & 7));
        bAdr[nq] = (uint32_t)(s * 128 + chunk * 16);
    }

    float acc[2][8][4];
    #pragma unroll
    for (int mt = 0; mt < 2; mt++)
        #pragma unroll
        for (int nt = 0; nt < 8; nt++)
            #pragma unroll
            for (int i = 0; i < 4; i++) acc[mt][nt][i] = 0.f;

    #pragma unroll
    for (int s = 0; s < NST - 1; s++) {
        uint32_t aT = sbase + s * (2 * TILE_BYTES);
        uint32_t bT = aT + TILE_BYTES;
        const __half* sa = gA + s * BK;
        const __half* sb = gW + s * BK;
        cp16(aT + pOff0, sa);
        cp16(aT + pOff1, sa + 8);
        cp16(bT + pOff0, sb);
        cp16(bT + pOff1, sb + 8);
        cp_commit();
    }

    int stage = 0;
    int pstage = NST - 1;
    for (int kt = 0; kt < KT; kt++) {
        cp_wait<NST - 2>();
        __syncthreads();

        if (kt + NST - 1 < KT) {
            uint32_t aT = sbase + pstage * (2 * TILE_BYTES);
            uint32_t bT = aT + TILE_BYTES;
            const __half* sa = gA + (kt + NST - 1) * BK;
            const __half* sb = gW + (kt + NST - 1) * BK;
            cp16(aT + pOff0, sa);
            cp16(aT + pOff1, sa + 8);
            cp16(bT + pOff0, sb);
            cp16(bT + pOff1, sb + 8);
        }
        cp_commit();

        uint32_t ab = sbase + stage * (2 * TILE_BYTES);
        uint32_t bb = ab + TILE_BYTES;
        #pragma unroll
        for (int ks = 0; ks < 2; ks++) {
            uint32_t kx = ks ? 32u : 0u;
            uint32_t af0[4], af1[4];
            ldsm4(af0, ab + (aAdr[0] ^ kx));
            ldsm4(af1, ab + (aAdr[1] ^ kx));
            #pragma unroll
            for (int nq = 0; nq < 4; nq++) {
                uint32_t bf[4];
                ldsm4(bf, bb + (bAdr[nq] ^ kx));
                mma16(acc[0][2 * nq],     af0, bf[0], bf[1]);
                mma16(acc[0][2 * nq + 1], af0, bf[2], bf[3]);
                mma16(acc[1][2 * nq],     af1, bf[0], bf[1]);
                mma16(acc[1][2 * nq + 1], af1, bf[2], bf[3]);
            }
        }
        if (++stage == NST) stage = 0;
        if (++pstage == NST) pstage = 0;
    }

    #pragma unroll
    for (int mt = 0; mt < 2; mt++) {
        #pragma unroll
        for (int nt = 0; nt < 8; nt++) {
            int r = m0 + wm * 32 + mt * 16 + g;
            int c = n0 + wn * 64 + nt * 8 + 2 * tg;
            float bv0 = __ldg(&bias[c]), bv1 = __ldg(&bias[c + 1]);
            float v00 = acc[mt][nt][0] + bv0, v01 = acc[mt][nt][1] + bv1;
            float v10 = acc[mt][nt][2] + bv0, v11 = acc[mt][nt][3] + bv1;
            if (!fused) {
                *(float2*)&outf[(size_t)r * GN + c]       = make_float2(v00, v01);
                *(float2*)&outf[(size_t)(r + 8) * GN + c] = make_float2(v10, v11);
            } else {
                int b = r >> 11, l = r & 2047;
                int h = c >> 7, d = c & 127;
                size_t base2 = ((size_t)(b * H_HEADS + h) * SEQ + l) * DHEAD + d;
                __half2 h0 = __floats2half2_rn(v00, v01);
                __half2 h1 = __floats2half2_rn(v10, v11);
                *(__half2*)&outp[base2]                     = h0;
                *(__half2*)&outp[base2 + (size_t)8 * DHEAD] = h1;
            }
        }
    }
}

// ---------------------------------------------------------------------------
// Sliding-window flash attention, fp16 mma + ldmatrix, double-buffered
// cp.async K/V pipeline. Smem: 2 x (K 16KB + V 16KB) + P 16KB = 80KB.
// ---------------------------------------------------------------------------
#define ATT_SMEM 81920

__global__ __launch_bounds__(256, 1)
void attn_h16(const __half* __restrict__ qg, const __half* __restrict__ kg,
              const __half* __restrict__ vg, __half* __restrict__ aout)
{
    extern __shared__ __align__(16) char sm[];
    uint32_t sb = smem_u32(sm);
    uint32_t Ps = sb + 65536;

    int tid = threadIdx.x;
    int wid = tid >> 5, lane = tid & 31, g = lane >> 2, tg = lane & 3;
    int q0 = blockIdx.x * 128;
    int bh = blockIdx.y;
    const __half* qb = qg + (size_t)bh * SEQ * DHEAD;
    const __half* kb = kg + (size_t)bh * SEQ * DHEAD;
    const __half* vb = vg + (size_t)bh * SEQ * DHEAD;
    int b = bh >> 4, h = bh & 15;

    // ---- stage Q (128 x 256B) in buffer0 area, load fragments ----
    #pragma unroll
    for (int e = tid; e < 2048; e += 256) {
        int r = e >> 4, c = e & 15;
        uint4 v = *(const uint4*)&qb[(size_t)(q0 + r) * DHEAD + c * 8];
        *(uint4*)(sm + r * 256 + ((c ^ (r & 7)) * 16)) = v;
    }
    __syncthreads();

    uint32_t qa[8][4];
    {
        int qrow = wid * 16 + (lane & 7) + 8 * ((lane >> 3) & 1);
        #pragma unroll
        for (int ks = 0; ks < 8; ks++) {
            int c = ks * 2 + (lane >> 4);
            ldsm4(qa[ks], sb + qrow * 256 + ((c ^ (qrow & 7)) * 16));
        }
    }
    __syncthreads();

    // chunk list (diagonal first)
    const int offs[6] = {0, 1, -1, -2, -3, -4};
    int k0s[6], nch = 0;
    #pragma unroll
    for (int ci = 0; ci < 6; ci++) {
        int k0 = q0 + offs[ci] * 64;
        if (k0 >= 0) k0s[nch++] = k0;
    }

    auto issue_kv = [&](int k0, int bf) {
        uint32_t dbase = sb + (uint32_t)bf * 32768u;
        #pragma unroll
        for (int j = 0; j < 8; j++) {
            int e = tid + j * 256;
            int which = e >> 10, i = e & 1023;
            int r = i >> 4, c = i & 15;
            const __half* src = which ? vb : kb;
            cp16(dbase + which * 16384 + (uint32_t)(r * 256 + ((c ^ (r & 7)) * 16)),
                 &src[(size_t)(k0 + r) * DHEAD + c * 8]);
        }
    };

    issue_kv(k0s[0], 0);
    cp_commit();

    float o[16][4];
    #pragma unroll
    for (int nt = 0; nt < 16; nt++)
        #pragma unroll
        for (int i = 0; i < 4; i++) o[nt][i] = 0.f;
    float mrow0 = -1e30f, mrow1 = -1e30f, lsum0 = 0.f, lsum1 = 0.f;

    const float scale = 0.088388347648318447f;

    int kRow = (lane & 7) + 8 * (lane >> 4);
    int kK8  = (lane >> 3) & 1;
    int pRow = wid * 16 + (lane & 7) + 8 * ((lane >> 3) & 1);
    int pK8  = lane >> 4;
    int vRow = (lane & 7) + 8 * ((lane >> 3) & 1);
    int vK8  = lane >> 4;
    int pr0 = wid * 16 + g, pr1 = pr0 + 8;

    for (int ci = 0; ci < nch; ci++) {
        int k0 = k0s[ci];
        __syncthreads();
        if (ci + 1 < nch) issue_kv(k0s[ci + 1], (ci + 1) & 1);
        cp_commit();
        cp_wait<1>();
        __syncthreads();

        uint32_t Ks = sb + (uint32_t)(ci & 1) * 32768u;
        uint32_t Vs = Ks + 16384u;

        // ---- S = Q K^T ----
        float s[8][4];
        #pragma unroll
        for (int nt = 0; nt < 8; nt++)
            #pragma unroll
            for (int i = 0; i < 4; i++) s[nt][i] = 0.f;
        #pragma unroll
        for (int ks = 0; ks < 8; ks++) {
            int c = ks * 2 + kK8;
            #pragma unroll
            for (int nq = 0; nq < 4; nq++) {
                int row = nq * 16 + kRow;
                uint32_t bf[4];
                ldsm4(bf, Ks + row * 256 + ((c ^ (row & 7)) * 16));
                mma16(s[2 * nq],     qa[ks], bf[0], bf[1]);
                mma16(s[2 * nq + 1], qa[ks], bf[2], bf[3]);
            }
        }

        // ---- mask + online softmax ----
        int i0 = q0 + pr0, i1 = i0 + 8;
        float mx0 = -1e30f, mx1 = -1e30f;
        #pragma unroll
        for (int nt = 0; nt < 8; nt++) {
            int j0 = k0 + nt * 8 + 2 * tg, j1 = j0 + 1;
            s[nt][0] = ((j0 <= i0) && (j0 > i0 - WIN)) ? s[nt][0] * scale : -1e30f;
            s[nt][1] = ((j1 <= i0) && (j1 > i0 - WIN)) ? s[nt][1] * scale : -1e30f;
            s[nt][2] = ((j0 <= i1) && (j0 > i1 - WIN)) ? s[nt][2] * scale : -1e30f;
            s[nt][3] = ((j1 <= i1) && (j1 > i1 - WIN)) ? s[nt][3] * scale : -1e30f;
            mx0 = fmaxf(mx0, fmaxf(s[nt][0], s[nt][1]));
            mx1 = fmaxf(mx1, fmaxf(s[nt][2], s[nt][3]));
        }
        mx0 = fmaxf(mx0, __shfl_xor_sync(0xffffffffu, mx0, 1));
        mx0 = fmaxf(mx0, __shfl_xor_sync(0xffffffffu, mx0, 2));
        mx1 = fmaxf(mx1, __shfl_xor_sync(0xffffffffu, mx1, 1));
        mx1 = fmaxf(mx1, __shfl_xor_sync(0xffffffffu, mx1, 2));
        float mn0 = fmaxf(mrow0, mx0), mn1 = fmaxf(mrow1, mx1);
        float al0 = __expf(mrow0 - mn0), al1 = __expf(mrow1 - mn1);
        mrow0 = mn0; mrow1 = mn1;

        float rs0 = 0.f, rs1 = 0.f;
        #pragma unroll
        for (int nt = 0; nt < 8; nt++) {
            s[nt][0] = __expf(s[nt][0] - mn0);
            s[nt][1] = __expf(s[nt][1] - mn0);
            s[nt][2] = __expf(s[nt][2] - mn1);
            s[nt][3] = __expf(s[nt][3] - mn1);
            rs0 += s[nt][0] + s[nt][1];
            rs1 += s[nt][2] + s[nt][3];
        }
        rs0 += __shfl_xor_sync(0xffffffffu, rs0, 1);
        rs0 += __shfl_xor_sync(0xffffffffu, rs0, 2);
        rs1 += __shfl_xor_sync(0xffffffffu, rs1, 1);
        rs1 += __shfl_xor_sync(0xffffffffu, rs1, 2);
        lsum0 = lsum0 * al0 + rs0;
        lsum1 = lsum1 * al1 + rs1;

        // ---- P -> fp16 smem (warp-private rows) ----
        #pragma unroll
        for (int nt = 0; nt < 8; nt++) {
            __half2 p0 = __floats2half2_rn(s[nt][0], s[nt][1]);
            __half2 p1 = __floats2half2_rn(s[nt][2], s[nt][3]);
            *(__half2*)(sm + 65536 + pr0 * 128 + ((nt ^ (pr0 & 7)) * 16) + 4 * tg) = p0;
            *(__half2*)(sm + 65536 + pr1 * 128 + ((nt ^ (pr1 & 7)) * 16) + 4 * tg) = p1;
        }
        __syncwarp();

        #pragma unroll
        for (int nt = 0; nt < 16; nt++) {
            o[nt][0] *= al0; o[nt][1] *= al0;
            o[nt][2] *= al1; o[nt][3] *= al1;
        }

        // ---- O += P V ----
        #pragma unroll
        for (int ks = 0; ks < 4; ks++) {
            uint32_t pa[4];
            {
                int c = ks * 2 + pK8;
                ldsm4(pa, Ps + pRow * 128 + ((c ^ (pRow & 7)) * 16));
            }
            int row = ks * 16 + vRow;
            uint32_t vbase = Vs + row * 256;
            int rx = row & 7;
            #pragma unroll
            for (int dt = 0; dt < 8; dt++) {
                int c = dt * 2 + vK8;
                uint32_t bf[4];
                ldsm4t(bf, vbase + ((c ^ rx) * 16));
                mma16(o[2 * dt],     pa, bf[0], bf[1]);
                mma16(o[2 * dt + 1], pa, bf[2], bf[3]);
            }
        }
    }

    float inv0 = 1.f / lsum0, inv1 = 1.f / lsum1;
    int t0 = q0 + pr0;
    #pragma unroll
    for (int nt = 0; nt < 16; nt++) {
        int col = h * DHEAD + nt * 8 + 2 * tg;
        __half2 h0 = __floats2half2_rn(o[nt][0] * inv0, o[nt][1] * inv0);
        __half2 h1 = __floats2half2_rn(o[nt][2] * inv1, o[nt][3] * inv1);
        *(__half2*)&aout[((size_t)b * SEQ + t0) * CDIM + col]     = h0;
        *(__half2*)&aout[((size_t)b * SEQ + t0 + 8) * CDIM + col] = h1;
    }
}

// ---------------------------------------------------------------------------
extern "C" void kernel_launch(void* const* d_in, const int* in_sizes, int n_in,
                              void* d_out, int out_size)
{
    const float* x  = (const float*)d_in[0];
    const float* Wq = (const float*)d_in[1];
    const float* bq = (const float*)d_in[2];
    const float* Wk = (const float*)d_in[3];
    const float* bk = (const float*)d_in[4];
    const float* Wv = (const float*)d_in[5];
    const float* bv = (const float*)d_in[6];
    const float* Wo = (const float*)d_in[7];
    const float* bo = (const float*)d_in[8];
    float* out = (float*)d_out;

    __half *qkvh, *xh, *wh, *aoh;
    cudaGetSymbolAddress((void**)&qkvh, g_qkvh);
    cudaGetSymbolAddress((void**)&xh, g_xh);
    cudaGetSymbolAddress((void**)&wh, g_wh);
    cudaGetSymbolAddress((void**)&aoh, g_aoh);

    cudaFuncSetAttribute(gemm_ca, cudaFuncAttributeMaxDynamicSharedMemorySize, GEMM_SMEM);
    cudaFuncSetAttribute(attn_h16, cudaFuncAttributeMaxDynamicSharedMemorySize, ATT_SMEM);

    // fused conversions: x (2^23) + 4 weights (4 * 2^22) = 25165824 elems
    cvt_all<<<(25165824 / 8) / 256, 256>>>(x, Wq, Wk, Wv, Wo, xh, wh);

    // fused QKV GEMM -> fp16 (B,H,L,D)
    gemm_ca<<<dim3(GM / TBM, 48), 256, GEMM_SMEM>>>(xh, wh, bq, bk, bv, nullptr, qkvh, 1);

    // attention (fp16 in, fp16 out)
    attn_h16<<<dim3(SEQ / 128, BATCH * H_HEADS), 256, ATT_SMEM>>>(
        qkvh, qkvh + QKV_ELEMS, qkvh + 2 * QKV_ELEMS, aoh);

    // output projection -> fp32
    gemm_ca<<<dim3(GM / TBM, GN / TBN), 256, GEMM_SMEM>>>(
        aoh, wh + 3 * WMAT_ELEMS, bo, nullptr, nullptr, out, nullptr, 0);
}

// round 13
// speedup vs baseline: 1.5094x; 1.0510x over previous
#include <cuda_runtime.h>
#include <cuda_fp16.h>
#include <cstdint>

#define H_HEADS 16
#define DHEAD 128
#define SEQ 2048
#define BATCH 2
#define CDIM 2048
#define WIN 256

#define GK 2048
#define GN 2048
#define GM 4096

#define QKV_ELEMS ((size_t)BATCH * H_HEADS * SEQ * DHEAD)   // 8388608
#define WMAT_ELEMS ((size_t)GK * GN)                        // 4194304 = 2^22
#define XEL (GM * GK)                                       // 8388608 = 2^23

// fp16 scratch
__device__ __half g_qkvh[3 * QKV_ELEMS];     // Q,K,V in (B,H,L,D)
__device__ __half g_xh[(size_t)XEL];
__device__ __half g_wh[4 * WMAT_ELEMS];      // Wq,Wk,Wv,Wo
__device__ __half g_aoh[(size_t)GM * CDIM];

// ---------------------------------------------------------------------------
__device__ __forceinline__ void mma16(float* c, const uint32_t* a, uint32_t b0, uint32_t b1) {
    asm volatile(
        "mma.sync.aligned.m16n8k16.row.col.f32.f16.f16.f32 "
        "{%0,%1,%2,%3},{%4,%5,%6,%7},{%8,%9},{%0,%1,%2,%3};\n"
        : "+f"(c[0]), "+f"(c[1]), "+f"(c[2]), "+f"(c[3])
        : "r"(a[0]), "r"(a[1]), "r"(a[2]), "r"(a[3]), "r"(b0), "r"(b1));
}

__device__ __forceinline__ void ldsm4(uint32_t* r, uint32_t addr) {
    asm volatile("ldmatrix.sync.aligned.m8n8.x4.shared.b16 {%0,%1,%2,%3}, [%4];"
                 : "=r"(r[0]), "=r"(r[1]), "=r"(r[2]), "=r"(r[3]) : "r"(addr));
}
__device__ __forceinline__ void ldsm4t(uint32_t* r, uint32_t addr) {
    asm volatile("ldmatrix.sync.aligned.m8n8.x4.trans.shared.b16 {%0,%1,%2,%3}, [%4];"
                 : "=r"(r[0]), "=r"(r[1]), "=r"(r[2]), "=r"(r[3]) : "r"(addr));
}

__device__ __forceinline__ uint32_t smem_u32(const void* p) {
    uint32_t a;
    asm("{ .reg .u64 t; cvta.to.shared.u64 t, %1; cvt.u32.u64 %0, t; }" : "=r"(a) : "l"(p));
    return a;
}

__device__ __forceinline__ void cp16(uint32_t dst, const void* src) {
    asm volatile("cp.async.cg.shared.global [%0], [%1], 16;\n" :: "r"(dst), "l"(src));
}
__device__ __forceinline__ void cp_commit() { asm volatile("cp.async.commit_group;\n"); }
template<int N> __device__ __forceinline__ void cp_wait() {
    asm volatile("cp.async.wait_group %0;\n" :: "n"(N));
}

// ---------------------------------------------------------------------------
// fused fp32 -> fp16 conversion: x (XEL elems) then 4 weight matrices
// ---------------------------------------------------------------------------
__global__ void cvt_all(const float* __restrict__ x,
                        const float* __restrict__ w0, const float* __restrict__ w1,
                        const float* __restrict__ w2, const float* __restrict__ w3,
                        __half* __restrict__ xh, __half* __restrict__ wh)
{
    int t = blockIdx.x * blockDim.x + threadIdx.x;
    size_t i = (size_t)t * 8;
    const float* in;
    __half* out;
    if (i < (size_t)XEL) {
        in = x + i;
        out = xh + i;
    } else {
        size_t j = i - XEL;
        int m = (int)(j >> 22);
        size_t r = j & (WMAT_ELEMS - 1);
        in = ((m == 0) ? w0 : (m == 1) ? w1 : (m == 2) ? w2 : w3) + r;
        out = wh + (size_t)m * WMAT_ELEMS + r;
    }
    float4 a = *(const float4*)in;
    float4 b = *(const float4*)(in + 4);
    __half2 h0 = __floats2half2_rn(a.x, a.y);
    __half2 h1 = __floats2half2_rn(a.z, a.w);
    __half2 h2 = __floats2half2_rn(b.x, b.y);
    __half2 h3 = __floats2half2_rn(b.z, b.w);
    *(uint4*)out = make_uint4(*(uint32_t*)&h0, *(uint32_t*)&h1,
                              *(uint32_t*)&h2, *(uint32_t*)&h3);
}

// ---------------------------------------------------------------------------
// FP16 GEMM, cp.async 6-stage pipeline + ldmatrix, 2 k-tiles per barrier.
// Tile 128x128x32, 8 warps (4x2). Smem tile: 64 rows x 128B; row s holds
// m-rows {2s,2s+1}; chunk = ((m&1)*4 + k8) ^ (s&7).
// Mainloop invariant (kt even): groups kt,kt+1 landed (wait<2>), kt+2,kt+3 in
// flight; this iter writes stages (kt+4)%6,(kt+5)%6 = the stages read last
// iteration (safe after the sync).
// fused=1: grid.y in [0,48): matrix mi=y/16 -> fp16 scatter (B,H,L,D).
// fused=0: fp32 row-major out.
// ---------------------------------------------------------------------------
#define TBM 128
#define TBN 128
#define BK 32
#define KT (GK / BK)      // 64
#define TILE_BYTES 8192
#define NST 6
#define PRO 4             // prologue stages
#define GEMM_SMEM (NST * 2 * TILE_BYTES)   // 96 KB

__global__ __launch_bounds__(256, 2)
void gemm_ca(const __half* __restrict__ A, const __half* __restrict__ Wh,
             const float* __restrict__ bias0, const float* __restrict__ bias1,
             const float* __restrict__ bias2,
             float* __restrict__ outf, __half* __restrict__ outh, int fused)
{
    extern __shared__ __align__(16) char smem[];
    uint32_t sbase = smem_u32(smem);

    int tid = threadIdx.x;
    int wid = tid >> 5, lane = tid & 31;
    int g = lane >> 2, tg = lane & 3;
    int wm = wid >> 1, wn = wid & 1;
    int m0 = blockIdx.x * TBM;

    int n0;
    const float* bias = bias0;
    const __half* W = Wh;
    __half* outp = outh;
    if (fused) {
        int mi = blockIdx.y >> 4;
        n0 = (blockIdx.y & 15) * TBN;
        W = Wh + (size_t)mi * WMAT_ELEMS;
        bias = (mi == 0) ? bias0 : (mi == 1) ? bias1 : bias2;
        outp = outh + (size_t)mi * QKV_ELEMS;
    } else {
        n0 = blockIdx.y * TBN;
    }

    int pm = tid >> 1;
    int ps = pm >> 1;
    int pre0 = (pm & 1) * 4 + (tid & 1) * 2;
    uint32_t pOff0 = (uint32_t)(ps * 128 + ((pre0 ^ (ps & 7)) * 16));
    uint32_t pOff1 = (uint32_t)(ps * 128 + (((pre0 + 1) ^ (ps & 7)) * 16));
    const __half* gA = A + (size_t)(m0 + pm) * GK + (tid & 1) * 16;
    const __half* gW = W + (size_t)(n0 + pm) * GK + (tid & 1) * 16;

    uint32_t aAdr[2], bAdr[4];
    #pragma unroll
    for (int mt = 0; mt < 2; mt++) {
        int m = wm * 32 + mt * 16 + (lane & 7) + 8 * ((lane >> 3) & 1);
        int k8 = lane >> 4;
        int s = m >> 1;
        int chunk = (((m & 1) * 4 + k8) ^ (s & 7));
        aAdr[mt] = (uint32_t)(s * 128 + chunk * 16);
    }
    #pragma unroll
    for (int nq = 0; nq < 4; nq++) {
        int n = wn * 64 + nq * 16 + (lane & 7) + 8 * (lane >> 4);
        int k8 = (lane >> 3) & 1;
        int s = n >> 1;
        int chunk = (((n & 1) * 4 + k8) ^ (s & 7));
        bAdr[nq] = (uint32_t)(s * 128 + chunk * 16);
    }

    float acc[2][8][4];
    #pragma unroll
    for (int mt = 0; mt < 2; mt++)
        #pragma unroll
        for (int nt = 0; nt < 8; nt++)
            #pragma unroll
            for (int i = 0; i < 4; i++) acc[mt][nt][i] = 0.f;

    // prologue: stages 0..3
    #pragma unroll
    for (int s = 0; s < PRO; s++) {
        uint32_t aT = sbase + s * (2 * TILE_BYTES);
        uint32_t bT = aT + TILE_BYTES;
        const __half* sa = gA + s * BK;
        const __half* sb = gW + s * BK;
        cp16(aT + pOff0, sa);
        cp16(aT + pOff1, sa + 8);
        cp16(bT + pOff0, sb);
        cp16(bT + pOff1, sb + 8);
        cp_commit();
    }

    int st0 = 0;            // stage of tile kt
    int wr0 = PRO;          // stage of tile kt+4
    for (int kt = 0; kt < KT; kt += 2) {
        cp_wait<2>();       // groups kt, kt+1 landed
        __syncthreads();

        // --- prefetch kt+4 ; compute kt ---
        if (kt + PRO < KT) {
            uint32_t aT = sbase + wr0 * (2 * TILE_BYTES);
            uint32_t bT = aT + TILE_BYTES;
            const __half* sa = gA + (kt + PRO) * BK;
            const __half* sb = gW + (kt + PRO) * BK;
            cp16(aT + pOff0, sa);
            cp16(aT + pOff1, sa + 8);
            cp16(bT + pOff0, sb);
            cp16(bT + pOff1, sb + 8);
        }
        cp_commit();
        {
            uint32_t ab = sbase + st0 * (2 * TILE_BYTES);
            uint32_t bb = ab + TILE_BYTES;
            #pragma unroll
            for (int ks = 0; ks < 2; ks++) {
                uint32_t kx = ks ? 32u : 0u;
                uint32_t af0[4], af1[4];
                ldsm4(af0, ab + (aAdr[0] ^ kx));
                ldsm4(af1, ab + (aAdr[1] ^ kx));
                #pragma unroll
                for (int nq = 0; nq < 4; nq++) {
                    uint32_t bf[4];
                    ldsm4(bf, bb + (bAdr[nq] ^ kx));
                    mma16(acc[0][2 * nq],     af0, bf[0], bf[1]);
                    mma16(acc[0][2 * nq + 1], af0, bf[2], bf[3]);
                    mma16(acc[1][2 * nq],     af1, bf[0], bf[1]);
                    mma16(acc[1][2 * nq + 1], af1, bf[2], bf[3]);
                }
            }
        }

        // --- prefetch kt+5 ; compute kt+1 ---
        int st1 = st0 + 1; if (st1 == NST) st1 = 0;
        int wr1 = wr0 + 1; if (wr1 == NST) wr1 = 0;
        if (kt + PRO + 1 < KT) {
            uint32_t aT = sbase + wr1 * (2 * TILE_BYTES);
            uint32_t bT = aT + TILE_BYTES;
            const __half* sa = gA + (kt + PRO + 1) * BK;
            const __half* sb = gW + (kt + PRO + 1) * BK;
            cp16(aT + pOff0, sa);
            cp16(aT + pOff1, sa + 8);
            cp16(bT + pOff0, sb);
            cp16(bT + pOff1, sb + 8);
        }
        cp_commit();
        {
            uint32_t ab = sbase + st1 * (2 * TILE_BYTES);
            uint32_t bb = ab + TILE_BYTES;
            #pragma unroll
            for (int ks = 0; ks < 2; ks++) {
                uint32_t kx = ks ? 32u : 0u;
                uint32_t af0[4], af1[4];
                ldsm4(af0, ab + (aAdr[0] ^ kx));
                ldsm4(af1, ab + (aAdr[1] ^ kx));
                #pragma unroll
                for (int nq = 0; nq < 4; nq++) {
                    uint32_t bf[4];
                    ldsm4(bf, bb + (bAdr[nq] ^ kx));
                    mma16(acc[0][2 * nq],     af0, bf[0], bf[1]);
                    mma16(acc[0][2 * nq + 1], af0, bf[2], bf[3]);
                    mma16(acc[1][2 * nq],     af1, bf[0], bf[1]);
                    mma16(acc[1][2 * nq + 1], af1, bf[2], bf[3]);
                }
            }
        }

        st0 += 2; if (st0 >= NST) st0 -= NST;
        wr0 += 2; if (wr0 >= NST) wr0 -= NST;
    }

    #pragma unroll
    for (int mt = 0; mt < 2; mt++) {
        #pragma unroll
        for (int nt = 0; nt < 8; nt++) {
            int r = m0 + wm * 32 + mt * 16 + g;
            int c = n0 + wn * 64 + nt * 8 + 2 * tg;
            float bv0 = __ldg(&bias[c]), bv1 = __ldg(&bias[c + 1]);
            float v00 = acc[mt][nt][0] + bv0, v01 = acc[mt][nt][1] + bv1;
            float v10 = acc[mt][nt][2] + bv0, v11 = acc[mt][nt][3] + bv1;
            if (!fused) {
                *(float2*)&outf[(size_t)r * GN + c]       = make_float2(v00, v01);
                *(float2*)&outf[(size_t)(r + 8) * GN + c] = make_float2(v10, v11);
            } else {
                int b = r >> 11, l = r & 2047;
                int h = c >> 7, d = c & 127;
                size_t base2 = ((size_t)(b * H_HEADS + h) * SEQ + l) * DHEAD + d;
                __half2 h0 = __floats2half2_rn(v00, v01);
                __half2 h1 = __floats2half2_rn(v10, v11);
                *(__half2*)&outp[base2]                     = h0;
                *(__half2*)&outp[base2 + (size_t)8 * DHEAD] = h1;
            }
        }
    }
}

// ---------------------------------------------------------------------------
// Sliding-window flash attention, fp16 mma + ldmatrix, double-buffered
// cp.async K/V pipeline. Smem: 2 x (K 16KB + V 16KB) + P 16KB = 80KB.
// ---------------------------------------------------------------------------
#define ATT_SMEM 81920

__global__ __launch_bounds__(256, 1)
void attn_h16(const __half* __restrict__ qg, const __half* __restrict__ kg,
              const __half* __restrict__ vg, __half* __restrict__ aout)
{
    extern __shared__ __align__(16) char sm[];
    uint32_t sb = smem_u32(sm);
    uint32_t Ps = sb + 65536;

    int tid = threadIdx.x;
    int wid = tid >> 5, lane = tid & 31, g = lane >> 2, tg = lane & 3;
    int q0 = blockIdx.x * 128;
    int bh = blockIdx.y;
    const __half* qb = qg + (size_t)bh * SEQ * DHEAD;
    const __half* kb = kg + (size_t)bh * SEQ * DHEAD;
    const __half* vb = vg + (size_t)bh * SEQ * DHEAD;
    int b = bh >> 4, h = bh & 15;

    // ---- stage Q (128 x 256B) in buffer0 area, load fragments ----
    #pragma unroll
    for (int e = tid; e < 2048; e += 256) {
        int r = e >> 4, c = e & 15;
        uint4 v = *(const uint4*)&qb[(size_t)(q0 + r) * DHEAD + c * 8];
        *(uint4*)(sm + r * 256 + ((c ^ (r & 7)) * 16)) = v;
    }
    __syncthreads();

    uint32_t qa[8][4];
    {
        int qrow = wid * 16 + (lane & 7) + 8 * ((lane >> 3) & 1);
        #pragma unroll
        for (int ks = 0; ks < 8; ks++) {
            int c = ks * 2 + (lane >> 4);
            ldsm4(qa[ks], sb + qrow * 256 + ((c ^ (qrow & 7)) * 16));
        }
    }
    __syncthreads();

    // chunk list (diagonal first)
    const int offs[6] = {0, 1, -1, -2, -3, -4};
    int k0s[6], nch = 0;
    #pragma unroll
    for (int ci = 0; ci < 6; ci++) {
        int k0 = q0 + offs[ci] * 64;
        if (k0 >= 0) k0s[nch++] = k0;
    }

    auto issue_kv = [&](int k0, int bf) {
        uint32_t dbase = sb + (uint32_t)bf * 32768u;
        #pragma unroll
        for (int j = 0; j < 8; j++) {
            int e = tid + j * 256;
            int which = e >> 10, i = e & 1023;
            int r = i >> 4, c = i & 15;
            const __half* src = which ? vb : kb;
            cp16(dbase + which * 16384 + (uint32_t)(r * 256 + ((c ^ (r & 7)) * 16)),
                 &src[(size_t)(k0 + r) * DHEAD + c * 8]);
        }
    };

    issue_kv(k0s[0], 0);
    cp_commit();

    float o[16][4];
    #pragma unroll
    for (int nt = 0; nt < 16; nt++)
        #pragma unroll
        for (int i = 0; i < 4; i++) o[nt][i] = 0.f;
    float mrow0 = -1e30f, mrow1 = -1e30f, lsum0 = 0.f, lsum1 = 0.f;

    const float scale = 0.088388347648318447f;

    int kRow = (lane & 7) + 8 * (lane >> 4);
    int kK8  = (lane >> 3) & 1;
    int pRow = wid * 16 + (lane & 7) + 8 * ((lane >> 3) & 1);
    int pK8  = lane >> 4;
    int vRow = (lane & 7) + 8 * ((lane >> 3) & 1);
    int vK8  = lane >> 4;
    int pr0 = wid * 16 + g, pr1 = pr0 + 8;

    for (int ci = 0; ci < nch; ci++) {
        int k0 = k0s[ci];
        __syncthreads();
        if (ci + 1 < nch) issue_kv(k0s[ci + 1], (ci + 1) & 1);
        cp_commit();
        cp_wait<1>();
        __syncthreads();

        uint32_t Ks = sb + (uint32_t)(ci & 1) * 32768u;
        uint32_t Vs = Ks + 16384u;

        // ---- S = Q K^T ----
        float s[8][4];
        #pragma unroll
        for (int nt = 0; nt < 8; nt++)
            #pragma unroll
            for (int i = 0; i < 4; i++) s[nt][i] = 0.f;
        #pragma unroll
        for (int ks = 0; ks < 8; ks++) {
            int c = ks * 2 + kK8;
            #pragma unroll
            for (int nq = 0; nq < 4; nq++) {
                int row = nq * 16 + kRow;
                uint32_t bf[4];
                ldsm4(bf, Ks + row * 256 + ((c ^ (row & 7)) * 16));
                mma16(s[2 * nq],     qa[ks], bf[0], bf[1]);
                mma16(s[2 * nq + 1], qa[ks], bf[2], bf[3]);
            }
        }

        // ---- mask + online softmax ----
        int i0 = q0 + pr0, i1 = i0 + 8;
        float mx0 = -1e30f, mx1 = -1e30f;
        #pragma unroll
        for (int nt = 0; nt < 8; nt++) {
            int j0 = k0 + nt * 8 + 2 * tg, j1 = j0 + 1;
            s[nt][0] = ((j0 <= i0) && (j0 > i0 - WIN)) ? s[nt][0] * scale : -1e30f;
            s[nt][1] = ((j1 <= i0) && (j1 > i0 - WIN)) ? s[nt][1] * scale : -1e30f;
            s[nt][2] = ((j0 <= i1) && (j0 > i1 - WIN)) ? s[nt][2] * scale : -1e30f;
            s[nt][3] = ((j1 <= i1) && (j1 > i1 - WIN)) ? s[nt][3] * scale : -1e30f;
            mx0 = fmaxf(mx0, fmaxf(s[nt][0], s[nt][1]));
            mx1 = fmaxf(mx1, fmaxf(s[nt][2], s[nt][3]));
        }
        mx0 = fmaxf(mx0, __shfl_xor_sync(0xffffffffu, mx0, 1));
        mx0 = fmaxf(mx0, __shfl_xor_sync(0xffffffffu, mx0, 2));
        mx1 = fmaxf(mx1, __shfl_xor_sync(0xffffffffu, mx1, 1));
        mx1 = fmaxf(mx1, __shfl_xor_sync(0xffffffffu, mx1, 2));
        float mn0 = fmaxf(mrow0, mx0), mn1 = fmaxf(mrow1, mx1);
        float al0 = __expf(mrow0 - mn0), al1 = __expf(mrow1 - mn1);
        mrow0 = mn0; mrow1 = mn1;

        float rs0 = 0.f, rs1 = 0.f;
        #pragma unroll
        for (int nt = 0; nt < 8; nt++) {
            s[nt][0] = __expf(s[nt][0] - mn0);
            s[nt][1] = __expf(s[nt][1] - mn0);
            s[nt][2] = __expf(s[nt][2] - mn1);
            s[nt][3] = __expf(s[nt][3] - mn1);
            rs0 += s[nt][0] + s[nt][1];
            rs1 += s[nt][2] + s[nt][3];
        }
        rs0 += __shfl_xor_sync(0xffffffffu, rs0, 1);
        rs0 += __shfl_xor_sync(0xffffffffu, rs0, 2);
        rs1 += __shfl_xor_sync(0xffffffffu, rs1, 1);
        rs1 += __shfl_xor_sync(0xffffffffu, rs1, 2);
        lsum0 = lsum0 * al0 + rs0;
        lsum1 = lsum1 * al1 + rs1;

        // ---- P -> fp16 smem (warp-private rows) ----
        #pragma unroll
        for (int nt = 0; nt < 8; nt++) {
            __half2 p0 = __floats2half2_rn(s[nt][0], s[nt][1]);
            __half2 p1 = __floats2half2_rn(s[nt][2], s[nt][3]);
            *(__half2*)(sm + 65536 + pr0 * 128 + ((nt ^ (pr0 & 7)) * 16) + 4 * tg) = p0;
            *(__half2*)(sm + 65536 + pr1 * 128 + ((nt ^ (pr1 & 7)) * 16) + 4 * tg) = p1;
        }
        __syncwarp();

        #pragma unroll
        for (int nt = 0; nt < 16; nt++) {
            o[nt][0] *= al0; o[nt][1] *= al0;
            o[nt][2] *= al1; o[nt][3] *= al1;
        }

        // ---- O += P V ----
        #pragma unroll
        for (int ks = 0; ks < 4; ks++) {
            uint32_t pa[4];
            {
                int c = ks * 2 + pK8;
                ldsm4(pa, Ps + pRow * 128 + ((c ^ (pRow & 7)) * 16));
            }
            int row = ks * 16 + vRow;
            uint32_t vbase = Vs + row * 256;
            int rx = row & 7;
            #pragma unroll
            for (int dt = 0; dt < 8; dt++) {
                int c = dt * 2 + vK8;
                uint32_t bf[4];
                ldsm4t(bf, vbase + ((c ^ rx) * 16));
                mma16(o[2 * dt],     pa, bf[0], bf[1]);
                mma16(o[2 * dt + 1], pa, bf[2], bf[3]);
            }
        }
    }

    float inv0 = 1.f / lsum0, inv1 = 1.f / lsum1;
    int t0 = q0 + pr0;
    #pragma unroll
    for (int nt = 0; nt < 16; nt++) {
        int col = h * DHEAD + nt * 8 + 2 * tg;
        __half2 h0 = __floats2half2_rn(o[nt][0] * inv0, o[nt][1] * inv0);
        __half2 h1 = __floats2half2_rn(o[nt][2] * inv1, o[nt][3] * inv1);
        *(__half2*)&aout[((size_t)b * SEQ + t0) * CDIM + col]     = h0;
        *(__half2*)&aout[((size_t)b * SEQ + t0 + 8) * CDIM + col] = h1;
    }
}

// ---------------------------------------------------------------------------
extern "C" void kernel_launch(void* const* d_in, const int* in_sizes, int n_in,
                              void* d_out, int out_size)
{
    const float* x  = (const float*)d_in[0];
    const float* Wq = (const float*)d_in[1];
    const float* bq = (const float*)d_in[2];
    const float* Wk = (const float*)d_in[3];
    const float* bk = (const float*)d_in[4];
    const float* Wv = (const float*)d_in[5];
    const float* bv = (const float*)d_in[6];
    const float* Wo = (const float*)d_in[7];
    const float* bo = (const float*)d_in[8];
    float* out = (float*)d_out;

    __half *qkvh, *xh, *wh, *aoh;
    cudaGetSymbolAddress((void**)&qkvh, g_qkvh);
    cudaGetSymbolAddress((void**)&xh, g_xh);
    cudaGetSymbolAddress((void**)&wh, g_wh);
    cudaGetSymbolAddress((void**)&aoh, g_aoh);

    cudaFuncSetAttribute(gemm_ca, cudaFuncAttributeMaxDynamicSharedMemorySize, GEMM_SMEM);
    cudaFuncSetAttribute(attn_h16, cudaFuncAttributeMaxDynamicSharedMemorySize, ATT_SMEM);

    // fused conversions: x (2^23) + 4 weights (4 * 2^22) = 25165824 elems
    cvt_all<<<(25165824 / 8) / 256, 256>>>(x, Wq, Wk, Wv, Wo, xh, wh);

    // fused QKV GEMM -> fp16 (B,H,L,D)
    gemm_ca<<<dim3(GM / TBM, 48), 256, GEMM_SMEM>>>(xh, wh, bq, bk, bv, nullptr, qkvh, 1);

    // attention (fp16 in, fp16 out)
    attn_h16<<<dim3(SEQ / 128, BATCH * H_HEADS), 256, ATT_SMEM>>>(
        qkvh, qkvh + QKV_ELEMS, qkvh + 2 * QKV_ELEMS, aoh);

    // output projection -> fp32
    gemm_ca<<<dim3(GM / TBM, GN / TBN), 256, GEMM_SMEM>>>(
        aoh, wh + 3 * WMAT_ELEMS, bo, nullptr, nullptr, out, nullptr, 0);
}